// round 1
// baseline (speedup 1.0000x reference)
#include <cuda_runtime.h>
#include <cuda_bf16.h>
#include <math.h>

#define BATCH 32
#define HW    512
#define NPIX  (HW*HW)
#define ROWS  16                // rows per strip
#define NSTRIPS (HW/ROWS)       // 32
#define WPR   16                // 32-bit mask words per row (512/32)
#define NTHR  254

// ---------------- device scratch (static, no allocation) ----------------
__device__ unsigned g_hist[BATCH * 256];
__device__ unsigned g_cnt[BATCH];
__device__ float    g_sq[BATCH];
__device__ float    g_t1[BATCH];
__device__ float    g_t2[BATCH];
__device__ unsigned g_maskwords[BATCH][HW * WPR];   // 1 MB bit-packed dilated mask

// ---------------- init: zero accumulators ----------------
__global__ void initKernel() {
    int t = blockIdx.x * blockDim.x + threadIdx.x;
    if (t < BATCH * 256) g_hist[t] = 0u;
    if (t < BATCH) { g_cnt[t] = 0u; g_sq[t] = 0.0f; }
}

// ---------------- kernel A: dilation (bitwise) + masked histogram + mask count ----------------
__global__ __launch_bounds__(256) void maskHistKernel(const float* __restrict__ labels,
                                                      const float* __restrict__ images) {
    const int b = blockIdx.y, strip = blockIdx.x;
    const int row0 = strip * ROWS;
    const int tid = threadIdx.x, lane = tid & 31, warp = tid >> 5;

    __shared__ unsigned lw[(ROWS + 4) * WPR];   // label bits (rows row0-2 .. row0+ROWS+1)
    __shared__ unsigned hw[(ROWS + 4) * WPR];   // horizontally dilated bits
    __shared__ unsigned sh_hist[256];
    sh_hist[tid] = 0u;

    const float* lab = labels + (size_t)b * NPIX;
    const float* img = images + (size_t)b * NPIX;

    const int NLW = (ROWS + 4) * WPR;           // 320 words
    for (int widx = warp; widx < NLW; widx += 8) {
        int r = widx >> 4, wc = widx & 15;
        int grow = row0 - 2 + r;
        float v = 0.0f;
        if (grow >= 0 && grow < HW) v = lab[grow * HW + wc * 32 + lane];
        unsigned bal = __ballot_sync(0xffffffffu, v > 0.0f);
        if (lane == 0) lw[widx] = bal;
    }
    __syncthreads();

    // horizontal dilation radius 2 (zero padding at image edges)
    for (int widx = tid; widx < NLW; widx += 256) {
        int wc = widx & 15;
        unsigned C = lw[widx];
        unsigned L = wc ? lw[widx - 1] : 0u;
        unsigned R = (wc < 15) ? lw[widx + 1] : 0u;
        hw[widx] = C | (C << 1) | (C << 2) | (C >> 1) | (C >> 2)
                 | (L >> 31) | (L >> 30) | (R << 31) | (R << 30);
    }
    __syncthreads();

    const float SCALEF = (float)(256.0 / 255.0);
    unsigned cnt = 0;
    // vertical dilation radius 2 + histogram; warp <-> mask word so skips are warp-uniform
    for (int widx = warp; widx < ROWS * WPR; widx += 8) {
        int r = widx >> 4, wc = widx & 15;
        unsigned m = hw[r * WPR + wc] | hw[(r + 1) * WPR + wc] | hw[(r + 2) * WPR + wc]
                   | hw[(r + 3) * WPR + wc] | hw[(r + 4) * WPR + wc];
        if (lane == 0) g_maskwords[b][(row0 + r) * WPR + wc] = m;
        if (m) {
            float v = img[(row0 + r) * HW + wc * 32 + lane];
            if ((m >> lane) & 1u) {
                // idx = clip(floor((img*255) * (256/255)), 0, 255)  -- same op order as reference
                float v255 = v * 255.0f;
                int idx = (int)floorf(v255 * SCALEF);
                idx = idx < 0 ? 0 : (idx > 255 ? 255 : idx);
                atomicAdd(&sh_hist[idx], 1u);
                cnt++;
            }
        }
    }
    __syncthreads();

    if (sh_hist[tid]) atomicAdd(&g_hist[b * 256 + tid], sh_hist[tid]);
    #pragma unroll
    for (int o = 16; o; o >>= 1) cnt += __shfl_down_sync(0xffffffffu, cnt, o);
    if (lane == 0 && cnt) atomicAdd(&g_cnt[b], cnt);
}

// ---------------- kernel B: two-threshold Otsu per batch ----------------
__global__ __launch_bounds__(256) void otsuKernel() {
    const int b = blockIdx.x, tid = threadIdx.x;
    __shared__ float h[256];     // normalized histogram
    __shared__ float a[256];     // cumsum(h)
    __shared__ float cm[256];    // cumsum(h * i)
    __shared__ float sbest[256];
    __shared__ int   sidx[256];

    float total = (float)g_cnt[b];            // exact (integer < 2^24)
    h[tid] = (float)g_hist[b * 256 + tid] / total;
    __syncthreads();

    if (tid == 0) {
        float c = 0.0f, c2 = 0.0f;
        for (int i = 0; i < 256; i++) {
            c  += h[i];          a[i]  = c;
            c2 += h[i] * (float)i; cm[i] = c2;
        }
    }
    __syncthreads();

    const float tm = cm[255];
    const float s = 1e-8f;
    float best = -1.0f;                       // bv >= 0 always
    int bestidx = 0x7fffffff;
    for (int flat = tid; flat < NTHR * NTHR; flat += 256) {
        int i = flat / NTHR, j = flat % NTHR;
        float w0 = a[i], cb = a[j];
        float w1 = cb - w0, w2 = 1.0f - cb;
        float m0 = cm[i], m1 = cm[j];
        float mean0 = m0 / (w0 + s);
        float mean1 = (m1 - m0) / (w1 + s);
        float mean2 = (tm - m1) / (w2 + s);
        float d0 = mean0 - tm, d1 = mean1 - tm, d2 = mean2 - tm;
        float bv = w0 * d0 * d0 + w1 * d1 * d1 + w2 * d2 * d2;
        bv = (w0 > 0.0f && w1 > 0.0f && w2 > 0.0f) ? bv : 0.0f;
        if (bv > best) { best = bv; bestidx = flat; }  // strided flat is increasing -> first max per thread
    }
    sbest[tid] = best; sidx[tid] = bestidx;
    __syncthreads();
    // reduce with first-occurrence (min flat index) tie-breaking to mimic jnp.argmax
    for (int st = 128; st; st >>= 1) {
        if (tid < st) {
            if (sbest[tid + st] > sbest[tid] ||
                (sbest[tid + st] == sbest[tid] && sidx[tid + st] < sidx[tid])) {
                sbest[tid] = sbest[tid + st];
                sidx[tid]  = sidx[tid + st];
            }
        }
        __syncthreads();
    }
    if (tid == 0) {
        int am = sidx[0];
        g_t1[b] = (float)(am / NTHR + 1) / 255.0f;
        g_t2[b] = (float)(am % NTHR + 1) / 255.0f;
    }
}

// ---------------- kernel C: masked squared-error accumulation ----------------
__global__ __launch_bounds__(256) void lossKernel(const float* __restrict__ preds,
                                                  const float* __restrict__ images) {
    const int b = blockIdx.y, strip = blockIdx.x;
    const int row0 = strip * ROWS;
    const int tid = threadIdx.x, lane = tid & 31, warp = tid >> 5;
    const float t1 = g_t1[b], t2 = g_t2[b];
    const size_t base = (size_t)b * NPIX;

    float acc = 0.0f;
    for (int widx = warp; widx < ROWS * WPR; widx += 8) {
        int r = widx >> 4, wc = widx & 15;
        unsigned m = g_maskwords[b][(row0 + r) * WPR + wc];
        if (!m) continue;                      // warp-uniform skip: no img/pred traffic
        if ((m >> lane) & 1u) {
            size_t off = base + (size_t)(row0 + r) * HW + wc * 32 + lane;
            float im = images[off];
            float cp = preds[off];
            float ci = (im >= t2) ? 1.0f : ((im >= t1) ? 0.5f : 0.0f);
            float d = ci - cp;
            acc = fmaf(d, d, acc);
        }
    }
    #pragma unroll
    for (int o = 16; o; o >>= 1) acc += __shfl_down_sync(0xffffffffu, acc, o);
    __shared__ float wsum[8];
    if (lane == 0) wsum[warp] = acc;
    __syncthreads();
    if (warp == 0) {
        float v = (lane < 8) ? wsum[lane] : 0.0f;
        #pragma unroll
        for (int o = 4; o; o >>= 1) v += __shfl_down_sync(0xffffffffu, v, o);
        if (lane == 0 && v != 0.0f) atomicAdd(&g_sq[b], v);
    }
}

// ---------------- kernel D: final scalar ----------------
__global__ void finalKernel(float* __restrict__ out) {
    int b = threadIdx.x;                       // 32 threads
    float sm = (float)g_cnt[b] + 1e-8f;        // mask-sum + eps, matches reference
    bool valid = sm > 1e-8f;
    float lp = valid ? (g_sq[b] / sm) : 0.0f;
    int c = valid ? 1 : 0;
    #pragma unroll
    for (int o = 16; o; o >>= 1) {
        lp += __shfl_down_sync(0xffffffffu, lp, o);
        c  += __shfl_down_sync(0xffffffffu, c, o);
    }
    if (b == 0) out[0] = (c > 0) ? (lp / (float)(c > 1 ? c : 1)) : 0.0f;
}

// ---------------- launch ----------------
extern "C" void kernel_launch(void* const* d_in, const int* in_sizes, int n_in,
                              void* d_out, int out_size) {
    const float* preds  = (const float*)d_in[0];
    const float* labels = (const float*)d_in[1];
    const float* images = (const float*)d_in[2];
    float* out = (float*)d_out;
    (void)in_sizes; (void)n_in; (void)out_size;

    initKernel<<<32, 256>>>();
    dim3 grid(NSTRIPS, BATCH);
    maskHistKernel<<<grid, 256>>>(labels, images);
    otsuKernel<<<BATCH, 256>>>();
    lossKernel<<<grid, 256>>>(preds, images);
    finalKernel<<<1, 32>>>(out);
}

// round 2
// speedup vs baseline: 1.4196x; 1.4196x over previous
#include <cuda_runtime.h>
#include <cuda_bf16.h>
#include <math.h>

#define BATCH 32
#define HW    512
#define NPIX  (HW*HW)
#define ROWS  32                 // rows per strip
#define NSTRIPS (HW/ROWS)        // 16
#define WPR   16                 // 32-bit mask words per row
#define NTHR  254
#define HALO  (ROWS + 4)         // 36 rows incl. +/-2 halo
#define NLW   (HALO * WPR)       // 576 words

// ---------------- device scratch (static, no allocation) ----------------
__device__ unsigned g_hist[BATCH * 256];
__device__ unsigned g_cnt[BATCH];
__device__ float    g_sq[BATCH];
__device__ float    g_t1[BATCH];
__device__ float    g_t2[BATCH];
__device__ unsigned g_maskwords[BATCH][HW * WPR];   // 1 MB bit-packed dilated mask

// ---------------- init: zero accumulators ----------------
__global__ void initKernel() {
    int t = blockIdx.x * blockDim.x + threadIdx.x;
    if (t < BATCH * 256) g_hist[t] = 0u;
    if (t < BATCH) { g_cnt[t] = 0u; g_sq[t] = 0.0f; }
}

// ---------------- kernel A: dilation (bitwise) + masked histogram + count ----------------
__global__ __launch_bounds__(256) void maskHistKernel(const float* __restrict__ labels,
                                                      const float* __restrict__ images) {
    const int b = blockIdx.y, strip = blockIdx.x;
    const int row0 = strip * ROWS;
    const int tid = threadIdx.x, lane = tid & 31, warp = tid >> 5;

    __shared__ unsigned lw[NLW];       // packed label bits (halo rows)
    __shared__ unsigned hwv[NLW];      // horizontally dilated
    __shared__ unsigned sh_hist[256];
    sh_hist[tid] = 0u;
    for (int i = tid; i < NLW; i += 256) lw[i] = 0u;
    __syncthreads();

    const float4* lab4 = (const float4*)(labels + (size_t)b * NPIX);
    const float4* img4 = (const float4*)(images + (size_t)b * NPIX);

    // phase 1: pack label bits, float4 loads, atomicOr only for nonzero nibbles (~2%)
    for (int q = tid; q < HALO * 128; q += 256) {
        int r = q >> 7, c4 = q & 127;
        int grow = row0 - 2 + r;
        if (grow >= 0 && grow < HW) {
            float4 v = __ldg(lab4 + grow * 128 + c4);
            unsigned nib = (unsigned)(v.x > 0.0f) | ((unsigned)(v.y > 0.0f) << 1)
                         | ((unsigned)(v.z > 0.0f) << 2) | ((unsigned)(v.w > 0.0f) << 3);
            if (nib) atomicOr(&lw[r * WPR + (c4 >> 3)], nib << ((c4 & 7) * 4));
        }
    }
    __syncthreads();

    // phase 2: horizontal dilation radius 2
    for (int widx = tid; widx < NLW; widx += 256) {
        int wc = widx & 15;
        unsigned C = lw[widx];
        unsigned L = wc ? lw[widx - 1] : 0u;
        unsigned R = (wc < 15) ? lw[widx + 1] : 0u;
        hwv[widx] = C | (C << 1) | (C << 2) | (C >> 1) | (C >> 2)
                  | (L >> 31) | (L >> 30) | (R << 31) | (R << 30);
    }
    __syncthreads();

    // phase 3: vertical OR + mask store + histogram (float4, nibble-predicated)
    const float SCALEF = 256.0f / 255.0f;
    unsigned cnt = 0;
    for (int g = warp; g < ROWS * WPR / 4; g += 8) {        // 128 groups of 4 words
        int widx = g * 4 + (lane >> 3);
        int r = widx >> 4, wc = widx & 15;
        int base = r * WPR + wc;                            // halo rows r..r+4
        unsigned m = hwv[base] | hwv[base + 16] | hwv[base + 32]
                   | hwv[base + 48] | hwv[base + 64];
        if ((lane & 7) == 0) g_maskwords[b][(row0 + r) * WPR + wc] = m;
        unsigned nib = (m >> ((lane & 7) * 4)) & 0xFu;
        cnt += __popc(nib);
        if (__any_sync(0xffffffffu, nib)) {
            if (nib) {
                float4 v = __ldg(img4 + (row0 + r) * 128 + wc * 8 + (lane & 7));
                float vs[4] = {v.x, v.y, v.z, v.w};
                #pragma unroll
                for (int k = 0; k < 4; k++) if (nib & (1u << k)) {
                    float v255 = vs[k] * 255.0f;
                    int idx = (int)floorf(v255 * SCALEF);
                    idx = idx < 0 ? 0 : (idx > 255 ? 255 : idx);
                    atomicAdd(&sh_hist[idx], 1u);
                }
            }
        }
    }
    __syncthreads();

    if (sh_hist[tid]) atomicAdd(&g_hist[b * 256 + tid], sh_hist[tid]);
    #pragma unroll
    for (int o = 16; o; o >>= 1) cnt += __shfl_down_sync(0xffffffffu, cnt, o);
    if (lane == 0 && cnt) atomicAdd(&g_cnt[b], cnt);
}

// ---------------- kernel B: two-threshold Otsu, hoisted (1 div in inner loop) ----------------
__global__ __launch_bounds__(256) void otsuKernel() {
    const int b = blockIdx.x, tid = threadIdx.x;
    __shared__ float h[256], a[256], cmv[256];
    __shared__ float term2[NTHR];
    __shared__ unsigned char w2pos[NTHR];
    __shared__ float sbest[256];
    __shared__ int   sidx[256];

    float total = (float)g_cnt[b];            // exact integer
    h[tid] = (float)g_hist[b * 256 + tid] / total;
    __syncthreads();

    if (tid == 0) {                            // sequential cumsum matches jnp order
        float c = 0.0f, c2 = 0.0f;
        for (int i = 0; i < 256; i++) {
            c  += h[i];              a[i]   = c;
            c2 += h[i] * (float)i;   cmv[i] = c2;
        }
    }
    __syncthreads();

    const float tm = cmv[255];
    const float s = 1e-8f;
    if (tid < NTHR) {                          // per-j precompute
        float cb = a[tid], w2 = 1.0f - cb;
        float mean2 = (tm - cmv[tid]) / (w2 + s);
        float d2 = mean2 - tm;
        term2[tid] = w2 * (d2 * d2);
        w2pos[tid] = w2 > 0.0f;
    }
    __syncthreads();

    float best = -1.0f;
    int bflat = 0x7fffffff;
    if (tid < NTHR) {
        const int i = tid;
        float w0 = a[i], m0 = cmv[i];
        float mean0 = m0 / (w0 + s);
        float d0 = mean0 - tm;
        float term0 = w0 * (d0 * d0);
        bool p0 = w0 > 0.0f;
        for (int j = 0; j < NTHR; j++) {
            float w1 = a[j] - w0;
            float mean1 = (cmv[j] - m0) / (w1 + s);
            float d1 = mean1 - tm;
            float bv = term0 + w1 * (d1 * d1) + term2[j];
            bv = (p0 && w1 > 0.0f && w2pos[j]) ? bv : 0.0f;
            if (bv > best) { best = bv; bflat = i * NTHR + j; }   // first-max per row
        }
    }
    sbest[tid] = best; sidx[tid] = bflat;
    __syncthreads();
    for (int st = 128; st; st >>= 1) {         // min-flat tie-break == jnp.argmax
        if (tid < st) {
            if (sbest[tid + st] > sbest[tid] ||
                (sbest[tid + st] == sbest[tid] && sidx[tid + st] < sidx[tid])) {
                sbest[tid] = sbest[tid + st];
                sidx[tid]  = sidx[tid + st];
            }
        }
        __syncthreads();
    }
    if (tid == 0) {
        int am = sidx[0];
        g_t1[b] = (float)(am / NTHR + 1) / 255.0f;
        g_t2[b] = (float)(am % NTHR + 1) / 255.0f;
    }
}

// ---------------- kernel C: masked squared-error (float4, nibble-predicated) ----------------
__global__ __launch_bounds__(256) void lossKernel(const float* __restrict__ preds,
                                                  const float* __restrict__ images) {
    const int b = blockIdx.y, strip = blockIdx.x;
    const int row0 = strip * ROWS;
    const int tid = threadIdx.x, lane = tid & 31, warp = tid >> 5;
    const float t1 = g_t1[b], t2 = g_t2[b];
    const float4* img4 = (const float4*)images;
    const float4* prd4 = (const float4*)preds;
    const size_t base4 = (size_t)b * (NPIX / 4);

    float acc = 0.0f;
    for (int g = warp; g < ROWS * WPR / 4; g += 8) {
        int widx = g * 4 + (lane >> 3);
        int r = widx >> 4, wc = widx & 15;
        unsigned m = g_maskwords[b][(row0 + r) * WPR + wc];
        unsigned nib = (m >> ((lane & 7) * 4)) & 0xFu;
        if (__any_sync(0xffffffffu, nib)) {
            if (nib) {
                size_t off = base4 + (row0 + r) * 128 + wc * 8 + (lane & 7);
                float4 iv = __ldg(img4 + off);
                float4 pv = __ldg(prd4 + off);
                float is[4] = {iv.x, iv.y, iv.z, iv.w};
                float ps[4] = {pv.x, pv.y, pv.z, pv.w};
                #pragma unroll
                for (int k = 0; k < 4; k++) if (nib & (1u << k)) {
                    float ci = (is[k] >= t2) ? 1.0f : ((is[k] >= t1) ? 0.5f : 0.0f);
                    float d = ci - ps[k];
                    acc = fmaf(d, d, acc);
                }
            }
        }
    }
    #pragma unroll
    for (int o = 16; o; o >>= 1) acc += __shfl_down_sync(0xffffffffu, acc, o);
    __shared__ float wsum[8];
    if (lane == 0) wsum[warp] = acc;
    __syncthreads();
    if (warp == 0) {
        float v = (lane < 8) ? wsum[lane] : 0.0f;
        #pragma unroll
        for (int o = 4; o; o >>= 1) v += __shfl_down_sync(0xffffffffu, v, o);
        if (lane == 0 && v != 0.0f) atomicAdd(&g_sq[b], v);
    }
}

// ---------------- kernel D: final scalar ----------------
__global__ void finalKernel(float* __restrict__ out) {
    int b = threadIdx.x;                       // 32 threads
    float sm = (float)g_cnt[b] + 1e-8f;
    bool valid = sm > 1e-8f;
    float lp = valid ? (g_sq[b] / sm) : 0.0f;
    int c = valid ? 1 : 0;
    #pragma unroll
    for (int o = 16; o; o >>= 1) {
        lp += __shfl_down_sync(0xffffffffu, lp, o);
        c  += __shfl_down_sync(0xffffffffu, c, o);
    }
    if (b == 0) out[0] = (c > 0) ? (lp / (float)(c > 1 ? c : 1)) : 0.0f;
}

// ---------------- launch ----------------
extern "C" void kernel_launch(void* const* d_in, const int* in_sizes, int n_in,
                              void* d_out, int out_size) {
    const float* preds  = (const float*)d_in[0];
    const float* labels = (const float*)d_in[1];
    const float* images = (const float*)d_in[2];
    float* out = (float*)d_out;
    (void)in_sizes; (void)n_in; (void)out_size;

    initKernel<<<32, 256>>>();
    dim3 grid(NSTRIPS, BATCH);
    maskHistKernel<<<grid, 256>>>(labels, images);
    otsuKernel<<<BATCH, 256>>>();
    lossKernel<<<grid, 256>>>(preds, images);
    finalKernel<<<1, 32>>>(out);
}

// round 3
// speedup vs baseline: 1.5202x; 1.0708x over previous
#include <cuda_runtime.h>
#include <cuda_bf16.h>
#include <math.h>

#define BATCH 32
#define HW    512
#define NPIX  (HW*HW)            // 262144
#define WPR   16                 // 32-bit words per row (512/32)
#define WPB   (HW*WPR)           // 8192 words per batch image
#define GPB   (NPIX/4)           // 65536 float4-groups per batch
#define NTHR  254

#define R2    64                 // rows per dilate strip
#define NSTR2 (HW/R2)            // 8
#define HALO2 (R2+4)             // 68
#define NW2   (HALO2*WPR)        // 1088 halo words
#define SW2   (R2*WPR)           // 1024 strip words

#define WLB   8                  // worklist-consumer blocks per batch

// ---------------- device scratch (static, no allocation) ----------------
__device__ unsigned g_lw[BATCH * WPB];      // 1 MB packed label bits
__device__ unsigned g_wl[BATCH][GPB];       // 8 MB worklist (worst case safe)
__device__ unsigned g_wlcnt[BATCH];
__device__ unsigned g_hist[BATCH * 256];
__device__ unsigned g_cnt[BATCH];
__device__ float    g_sq[BATCH];
__device__ float    g_t1[BATCH];
__device__ float    g_t2[BATCH];

// ---------------- init ----------------
__global__ void initKernel() {
    int t = blockIdx.x * blockDim.x + threadIdx.x;
    if (t < BATCH * 256) g_hist[t] = 0u;
    if (t < BATCH) { g_cnt[t] = 0u; g_sq[t] = 0.0f; g_wlcnt[t] = 0u; }
}

// ---------------- K1: dense label bit-packing (pure streaming) ----------------
__global__ __launch_bounds__(256) void packKernel(const float* __restrict__ labels) {
    const int tid = threadIdx.x;
    __shared__ unsigned sw[256];
    sw[tid] = 0u;
    __syncthreads();

    const float4* lab4 = (const float4*)labels;
    const size_t gbase = (size_t)blockIdx.x * 2048;     // 2048 groups per block
    #pragma unroll
    for (int k = 0; k < 8; k++) {
        int li = k * 256 + tid;                          // local group 0..2047
        float4 v = __ldg(lab4 + gbase + li);
        unsigned nib = (unsigned)(v.x > 0.0f) | ((unsigned)(v.y > 0.0f) << 1)
                     | ((unsigned)(v.z > 0.0f) << 2) | ((unsigned)(v.w > 0.0f) << 3);
        if (nib) atomicOr(&sw[li >> 3], nib << ((li & 7) * 4));
    }
    __syncthreads();
    g_lw[blockIdx.x * 256 + tid] = sw[tid];
}

// ---------------- K2: bitwise 5x5 dilation + worklist build + mask count ----------------
__global__ __launch_bounds__(256) void dilateKernel() {
    const int b = blockIdx.y, strip = blockIdx.x;
    const int row0 = strip * R2;
    const int tid = threadIdx.x, lane = tid & 31, warp = tid >> 5;

    __shared__ unsigned lw[NW2];
    __shared__ unsigned hwv[NW2];
    __shared__ unsigned stage[SW2 * 8];      // worst-case all groups active
    __shared__ unsigned s_n;
    __shared__ unsigned s_base;
    if (tid == 0) s_n = 0u;

    const unsigned* lwb = g_lw + b * WPB;
    for (int w = tid; w < NW2; w += 256) {
        int r = w >> 4, wc = w & 15;
        int grow = row0 - 2 + r;
        lw[w] = (grow >= 0 && grow < HW) ? lwb[grow * WPR + wc] : 0u;
    }
    __syncthreads();

    for (int w = tid; w < NW2; w += 256) {
        int wc = w & 15;
        unsigned C = lw[w];
        unsigned L = wc ? lw[w - 1] : 0u;
        unsigned R = (wc < 15) ? lw[w + 1] : 0u;
        hwv[w] = C | (C << 1) | (C << 2) | (C >> 1) | (C >> 2)
               | (L >> 31) | (L >> 30) | (R << 31) | (R << 30);
    }
    __syncthreads();

    unsigned cnt = 0;
    for (int w = tid; w < SW2; w += 256) {
        int r = w >> 4, wc = w & 15;
        int hb = r * WPR + wc;
        unsigned m = hwv[hb] | hwv[hb + 16] | hwv[hb + 32] | hwv[hb + 48] | hwv[hb + 64];
        if (m) {
            cnt += __popc(m);
            unsigned gw = (row0 + r) * WPR + wc;     // global word index in batch
            #pragma unroll
            for (int k = 0; k < 8; k++) {
                unsigned nib = (m >> (k * 4)) & 0xFu;
                if (nib) {
                    unsigned pos = atomicAdd(&s_n, 1u);
                    stage[pos] = (nib << 16) | (gw * 8 + k);   // group < 65536
                }
            }
        }
    }
    __syncthreads();
    if (tid == 0) s_base = atomicAdd(&g_wlcnt[b], s_n);
    __syncthreads();
    unsigned n = s_n, basep = s_base;
    for (unsigned i = tid; i < n; i += 256) g_wl[b][basep + i] = stage[i];

    #pragma unroll
    for (int o = 16; o; o >>= 1) cnt += __shfl_down_sync(0xffffffffu, cnt, o);
    __shared__ unsigned wcnt[8];
    if (lane == 0) wcnt[warp] = cnt;
    __syncthreads();
    if (tid == 0) {
        unsigned t = 0;
        #pragma unroll
        for (int i = 0; i < 8; i++) t += wcnt[i];
        if (t) atomicAdd(&g_cnt[b], t);
    }
}

// ---------------- K3: histogram over worklist ----------------
__global__ __launch_bounds__(256) void histKernel(const float* __restrict__ images) {
    const int b = blockIdx.y, tid = threadIdx.x;
    __shared__ unsigned sh_hist[256];
    sh_hist[tid] = 0u;
    __syncthreads();

    const unsigned n = g_wlcnt[b];
    const float4* img4 = (const float4*)(images + (size_t)b * NPIX);
    const float SCALEF = 256.0f / 255.0f;

    for (unsigned i = blockIdx.x * 256 + tid; i < n; i += WLB * 256) {
        unsigned e = g_wl[b][i];
        unsigned g = e & 0xFFFFu, nib = e >> 16;
        float4 v = __ldg(img4 + g);
        float vs[4] = {v.x, v.y, v.z, v.w};
        #pragma unroll
        for (int k = 0; k < 4; k++) if (nib & (1u << k)) {
            float v255 = vs[k] * 255.0f;
            int idx = (int)floorf(v255 * SCALEF);
            idx = idx < 0 ? 0 : (idx > 255 ? 255 : idx);
            atomicAdd(&sh_hist[idx], 1u);
        }
    }
    __syncthreads();
    if (sh_hist[tid]) atomicAdd(&g_hist[b * 256 + tid], sh_hist[tid]);
}

// ---------------- K4: two-threshold Otsu (hoisted, 1 div inner) ----------------
__global__ __launch_bounds__(256) void otsuKernel() {
    const int b = blockIdx.x, tid = threadIdx.x;
    __shared__ float h[256], a[256], cmv[256];
    __shared__ float term2[NTHR];
    __shared__ unsigned char w2pos[NTHR];
    __shared__ float sbest[256];
    __shared__ int   sidx[256];

    float total = (float)g_cnt[b];
    h[tid] = (float)g_hist[b * 256 + tid] / total;
    __syncthreads();

    if (tid == 0) {                            // sequential cumsum == jnp order
        float c = 0.0f, c2 = 0.0f;
        for (int i = 0; i < 256; i++) {
            c  += h[i];              a[i]   = c;
            c2 += h[i] * (float)i;   cmv[i] = c2;
        }
    }
    __syncthreads();

    const float tm = cmv[255];
    const float s = 1e-8f;
    if (tid < NTHR) {
        float cb = a[tid], w2 = 1.0f - cb;
        float mean2 = (tm - cmv[tid]) / (w2 + s);
        float d2 = mean2 - tm;
        term2[tid] = w2 * (d2 * d2);
        w2pos[tid] = w2 > 0.0f;
    }
    __syncthreads();

    float best = -1.0f;
    int bflat = 0x7fffffff;
    if (tid < NTHR) {
        const int i = tid;
        float w0 = a[i], m0 = cmv[i];
        float mean0 = m0 / (w0 + s);
        float d0 = mean0 - tm;
        float term0 = w0 * (d0 * d0);
        bool p0 = w0 > 0.0f;
        for (int j = 0; j < NTHR; j++) {
            float w1 = a[j] - w0;
            float mean1 = (cmv[j] - m0) / (w1 + s);
            float d1 = mean1 - tm;
            float bv = term0 + w1 * (d1 * d1) + term2[j];
            bv = (p0 && w1 > 0.0f && w2pos[j]) ? bv : 0.0f;
            if (bv > best) { best = bv; bflat = i * NTHR + j; }
        }
    }
    sbest[tid] = best; sidx[tid] = bflat;
    __syncthreads();
    for (int st = 128; st; st >>= 1) {         // min-flat tie-break == jnp.argmax
        if (tid < st) {
            if (sbest[tid + st] > sbest[tid] ||
                (sbest[tid + st] == sbest[tid] && sidx[tid + st] < sidx[tid])) {
                sbest[tid] = sbest[tid + st];
                sidx[tid]  = sidx[tid + st];
            }
        }
        __syncthreads();
    }
    if (tid == 0) {
        int am = sidx[0];
        g_t1[b] = (float)(am / NTHR + 1) / 255.0f;
        g_t2[b] = (float)(am % NTHR + 1) / 255.0f;
    }
}

// ---------------- K5: masked squared-error over worklist ----------------
__global__ __launch_bounds__(256) void lossKernel(const float* __restrict__ preds,
                                                  const float* __restrict__ images) {
    const int b = blockIdx.y, tid = threadIdx.x;
    const int lane = tid & 31, warp = tid >> 5;
    const float t1 = g_t1[b], t2 = g_t2[b];
    const unsigned n = g_wlcnt[b];
    const float4* img4 = (const float4*)(images + (size_t)b * NPIX);
    const float4* prd4 = (const float4*)(preds  + (size_t)b * NPIX);

    float acc = 0.0f;
    for (unsigned i = blockIdx.x * 256 + tid; i < n; i += WLB * 256) {
        unsigned e = g_wl[b][i];
        unsigned g = e & 0xFFFFu, nib = e >> 16;
        float4 iv = __ldg(img4 + g);
        float4 pv = __ldg(prd4 + g);
        float is[4] = {iv.x, iv.y, iv.z, iv.w};
        float ps[4] = {pv.x, pv.y, pv.z, pv.w};
        #pragma unroll
        for (int k = 0; k < 4; k++) if (nib & (1u << k)) {
            float ci = (is[k] >= t2) ? 1.0f : ((is[k] >= t1) ? 0.5f : 0.0f);
            float d = ci - ps[k];
            acc = fmaf(d, d, acc);
        }
    }
    #pragma unroll
    for (int o = 16; o; o >>= 1) acc += __shfl_down_sync(0xffffffffu, acc, o);
    __shared__ float wsum[8];
    if (lane == 0) wsum[warp] = acc;
    __syncthreads();
    if (warp == 0) {
        float v = (lane < 8) ? wsum[lane] : 0.0f;
        #pragma unroll
        for (int o = 4; o; o >>= 1) v += __shfl_down_sync(0xffffffffu, v, o);
        if (lane == 0 && v != 0.0f) atomicAdd(&g_sq[b], v);
    }
}

// ---------------- K6: final scalar ----------------
__global__ void finalKernel(float* __restrict__ out) {
    int b = threadIdx.x;                       // 32 threads
    float sm = (float)g_cnt[b] + 1e-8f;
    bool valid = sm > 1e-8f;
    float lp = valid ? (g_sq[b] / sm) : 0.0f;
    int c = valid ? 1 : 0;
    #pragma unroll
    for (int o = 16; o; o >>= 1) {
        lp += __shfl_down_sync(0xffffffffu, lp, o);
        c  += __shfl_down_sync(0xffffffffu, c, o);
    }
    if (b == 0) out[0] = (c > 0) ? (lp / (float)(c > 1 ? c : 1)) : 0.0f;
}

// ---------------- launch ----------------
extern "C" void kernel_launch(void* const* d_in, const int* in_sizes, int n_in,
                              void* d_out, int out_size) {
    const float* preds  = (const float*)d_in[0];
    const float* labels = (const float*)d_in[1];
    const float* images = (const float*)d_in[2];
    float* out = (float*)d_out;
    (void)in_sizes; (void)n_in; (void)out_size;

    initKernel<<<32, 256>>>();
    packKernel<<<BATCH * GPB / 2048, 256>>>(labels);          // 1024 blocks
    dilateKernel<<<dim3(NSTR2, BATCH), 256>>>();              // 8 x 32
    histKernel<<<dim3(WLB, BATCH), 256>>>(images);            // 8 x 32
    otsuKernel<<<BATCH, 256>>>();
    lossKernel<<<dim3(WLB, BATCH), 256>>>(preds, images);     // 8 x 32
    finalKernel<<<1, 32>>>(out);
}

// round 4
// speedup vs baseline: 1.5751x; 1.0361x over previous
#include <cuda_runtime.h>
#include <cuda_bf16.h>
#include <math.h>

#define BATCH 32
#define HW    512
#define NPIX  (HW*HW)            // 262144
#define WPR   16                 // 32-bit words per row
#define G4PB  (NPIX/4)           // 65536 float4 groups per batch
#define NTHR  254

#define ROWS  32                 // rows per strip
#define NSTR  (HW/ROWS)          // 16 strips
#define HALO  (ROWS+4)           // 36
#define NLW   (HALO*WPR)         // 576 halo words
#define SW    (ROWS*WPR)         // 512 strip words
#define CAP   (SW*8)             // 4096 max worklist entries per strip

// ---------------- device scratch (all overwrite-style, no init needed) ----------------
__device__ unsigned g_wl[BATCH][NSTR][CAP];      // 8 MB worklist segments
__device__ unsigned g_wln[BATCH][NSTR];
__device__ unsigned g_histp[BATCH][NSTR][256];   // per-strip hist partials
__device__ unsigned g_cntp[BATCH][NSTR];
__device__ float    g_sqp[BATCH][NSTR];
__device__ float    g_t1[BATCH];
__device__ float    g_t2[BATCH];

// ---------------- K1: fused pack + dilate + worklist + histogram ----------------
__global__ __launch_bounds__(256) void fusedKernel(const float* __restrict__ labels,
                                                   const float* __restrict__ images) {
    const int b = blockIdx.y, strip = blockIdx.x;
    const int row0 = strip * ROWS;
    const int tid = threadIdx.x, lane = tid & 31, warp = tid >> 5;

    __shared__ unsigned lw[NLW];
    __shared__ unsigned hwv[NLW];
    __shared__ unsigned stage[CAP];
    __shared__ unsigned sh_hist[256];
    __shared__ unsigned s_n;
    __shared__ unsigned wcnt[8];

    sh_hist[tid] = 0u;
    if (tid == 0) s_n = 0u;
    for (int w = tid; w < NLW; w += 256) lw[w] = 0u;
    __syncthreads();

    // phase A: pack label bits from float4 stream (atomicOr fires ~2% of the time)
    const float4* lab4 = (const float4*)labels + (size_t)b * G4PB;
    for (int q = tid; q < HALO * 128; q += 256) {
        int r = q >> 7, c4 = q & 127;
        int grow = row0 - 2 + r;
        if (grow >= 0 && grow < HW) {
            float4 v = __ldg(lab4 + grow * 128 + c4);
            unsigned nib = (unsigned)(v.x > 0.0f) | ((unsigned)(v.y > 0.0f) << 1)
                         | ((unsigned)(v.z > 0.0f) << 2) | ((unsigned)(v.w > 0.0f) << 3);
            if (nib) atomicOr(&lw[r * WPR + (c4 >> 3)], nib << ((c4 & 7) * 4));
        }
    }
    __syncthreads();

    // phase B: horizontal dilation radius 2
    for (int w = tid; w < NLW; w += 256) {
        int wc = w & 15;
        unsigned C = lw[w];
        unsigned L = wc ? lw[w - 1] : 0u;
        unsigned R = (wc < 15) ? lw[w + 1] : 0u;
        hwv[w] = C | (C << 1) | (C << 2) | (C >> 1) | (C >> 2)
               | (L >> 31) | (L >> 30) | (R << 31) | (R << 30);
    }
    __syncthreads();

    // phase C: vertical OR + count + stage worklist entries
    unsigned cnt = 0;
    for (int w = tid; w < SW; w += 256) {
        int r = w >> 4, wc = w & 15;
        unsigned m = hwv[w] | hwv[w + 16] | hwv[w + 32] | hwv[w + 48] | hwv[w + 64];
        if (m) {
            cnt += __popc(m);
            unsigned gw = (row0 + r) * WPR + wc;
            #pragma unroll
            for (int k = 0; k < 8; k++) {
                unsigned nib = (m >> (k * 4)) & 0xFu;
                if (nib) {
                    unsigned pos = atomicAdd(&s_n, 1u);
                    stage[pos] = (nib << 16) | (gw * 8 + k);
                }
            }
        }
    }
    #pragma unroll
    for (int o = 16; o; o >>= 1) cnt += __shfl_down_sync(0xffffffffu, cnt, o);
    if (lane == 0) wcnt[warp] = cnt;
    __syncthreads();

    const unsigned n = s_n;
    // phase D: histogram from staged (dense) worklist + write segment to global
    const float4* img4 = (const float4*)images + (size_t)b * G4PB;
    const float SCALEF = 256.0f / 255.0f;
    for (unsigned i = tid; i < n; i += 256) {
        unsigned e = stage[i];
        g_wl[b][strip][i] = e;
        unsigned g = e & 0xFFFFu, nib = e >> 16;
        float4 v = __ldg(img4 + g);
        float vs[4] = {v.x, v.y, v.z, v.w};
        #pragma unroll
        for (int k = 0; k < 4; k++) if (nib & (1u << k)) {
            float v255 = vs[k] * 255.0f;
            int idx = (int)floorf(v255 * SCALEF);
            idx = idx < 0 ? 0 : (idx > 255 ? 255 : idx);
            atomicAdd(&sh_hist[idx], 1u);
        }
    }
    __syncthreads();

    g_histp[b][strip][tid] = sh_hist[tid];
    if (tid == 0) {
        unsigned t = 0;
        #pragma unroll
        for (int i = 0; i < 8; i++) t += wcnt[i];
        g_cntp[b][strip] = t;
        g_wln[b][strip] = n;
    }
}

// ---------------- K2: two-threshold Otsu (sums strip partials, hoisted inner) ----------------
__global__ __launch_bounds__(256) void otsuKernel() {
    const int b = blockIdx.x, tid = threadIdx.x;
    __shared__ float h[256], a[256], cmv[256];
    __shared__ float term2[NTHR];
    __shared__ unsigned char w2pos[NTHR];
    __shared__ float sbest[256];
    __shared__ int   sidx[256];
    __shared__ float s_total;

    unsigned hc = 0;
    #pragma unroll
    for (int s = 0; s < NSTR; s++) hc += g_histp[b][s][tid];
    if (tid == 0) {
        unsigned t = 0;
        #pragma unroll
        for (int s = 0; s < NSTR; s++) t += g_cntp[b][s];
        s_total = (float)t;
    }
    __syncthreads();
    h[tid] = (float)hc / s_total;
    __syncthreads();

    if (tid == 0) {                            // sequential cumsum == jnp order
        float c = 0.0f, c2 = 0.0f;
        for (int i = 0; i < 256; i++) {
            c  += h[i];              a[i]   = c;
            c2 += h[i] * (float)i;   cmv[i] = c2;
        }
    }
    __syncthreads();

    const float tm = cmv[255];
    const float s = 1e-8f;
    if (tid < NTHR) {
        float cb = a[tid], w2 = 1.0f - cb;
        float mean2 = (tm - cmv[tid]) / (w2 + s);
        float d2 = mean2 - tm;
        term2[tid] = w2 * (d2 * d2);
        w2pos[tid] = w2 > 0.0f;
    }
    __syncthreads();

    float best = -1.0f;
    int bflat = 0x7fffffff;
    if (tid < NTHR) {
        const int i = tid;
        float w0 = a[i], m0 = cmv[i];
        float mean0 = m0 / (w0 + s);
        float d0 = mean0 - tm;
        float term0 = w0 * (d0 * d0);
        bool p0 = w0 > 0.0f;
        for (int j = 0; j < NTHR; j++) {
            float w1 = a[j] - w0;
            float mean1 = (cmv[j] - m0) / (w1 + s);
            float d1 = mean1 - tm;
            float bv = term0 + w1 * (d1 * d1) + term2[j];
            bv = (p0 && w1 > 0.0f && w2pos[j]) ? bv : 0.0f;
            if (bv > best) { best = bv; bflat = i * NTHR + j; }
        }
    }
    sbest[tid] = best; sidx[tid] = bflat;
    __syncthreads();
    for (int st = 128; st; st >>= 1) {         // min-flat tie-break == jnp.argmax
        if (tid < st) {
            if (sbest[tid + st] > sbest[tid] ||
                (sbest[tid + st] == sbest[tid] && sidx[tid + st] < sidx[tid])) {
                sbest[tid] = sbest[tid + st];
                sidx[tid]  = sidx[tid + st];
            }
        }
        __syncthreads();
    }
    if (tid == 0) {
        int am = sidx[0];
        g_t1[b] = (float)(am / NTHR + 1) / 255.0f;
        g_t2[b] = (float)(am % NTHR + 1) / 255.0f;
    }
}

// ---------------- K3: masked squared-error over worklist segments ----------------
__global__ __launch_bounds__(256) void lossKernel(const float* __restrict__ preds,
                                                  const float* __restrict__ images) {
    const int b = blockIdx.y, strip = blockIdx.x;
    const int tid = threadIdx.x, lane = tid & 31, warp = tid >> 5;
    const float t1 = g_t1[b], t2 = g_t2[b];
    const unsigned n = g_wln[b][strip];
    const float4* img4 = (const float4*)images + (size_t)b * G4PB;
    const float4* prd4 = (const float4*)preds  + (size_t)b * G4PB;

    float acc = 0.0f;
    for (unsigned i = tid; i < n; i += 256) {
        unsigned e = g_wl[b][strip][i];
        unsigned g = e & 0xFFFFu, nib = e >> 16;
        float4 iv = __ldg(img4 + g);
        float4 pv = __ldg(prd4 + g);
        float is[4] = {iv.x, iv.y, iv.z, iv.w};
        float ps[4] = {pv.x, pv.y, pv.z, pv.w};
        #pragma unroll
        for (int k = 0; k < 4; k++) if (nib & (1u << k)) {
            float ci = (is[k] >= t2) ? 1.0f : ((is[k] >= t1) ? 0.5f : 0.0f);
            float d = ci - ps[k];
            acc = fmaf(d, d, acc);
        }
    }
    #pragma unroll
    for (int o = 16; o; o >>= 1) acc += __shfl_down_sync(0xffffffffu, acc, o);
    __shared__ float wsum[8];
    if (lane == 0) wsum[warp] = acc;
    __syncthreads();
    if (tid == 0) {
        float v = 0.0f;
        #pragma unroll
        for (int i = 0; i < 8; i++) v += wsum[i];
        g_sqp[b][strip] = v;
    }
}

// ---------------- K4: final scalar ----------------
__global__ void finalKernel(float* __restrict__ out) {
    int b = threadIdx.x;                       // 32 threads
    float sq = 0.0f; unsigned cnt = 0;
    #pragma unroll
    for (int s = 0; s < NSTR; s++) { sq += g_sqp[b][s]; cnt += g_cntp[b][s]; }
    float sm = (float)cnt + 1e-8f;
    bool valid = sm > 1e-8f;
    float lp = valid ? (sq / sm) : 0.0f;
    int c = valid ? 1 : 0;
    #pragma unroll
    for (int o = 16; o; o >>= 1) {
        lp += __shfl_down_sync(0xffffffffu, lp, o);
        c  += __shfl_down_sync(0xffffffffu, c, o);
    }
    if (b == 0) out[0] = (c > 0) ? (lp / (float)(c > 1 ? c : 1)) : 0.0f;
}

// ---------------- launch ----------------
extern "C" void kernel_launch(void* const* d_in, const int* in_sizes, int n_in,
                              void* d_out, int out_size) {
    const float* preds  = (const float*)d_in[0];
    const float* labels = (const float*)d_in[1];
    const float* images = (const float*)d_in[2];
    float* out = (float*)d_out;
    (void)in_sizes; (void)n_in; (void)out_size;

    dim3 grid(NSTR, BATCH);                    // 16 x 32 = 512 blocks
    fusedKernel<<<grid, 256>>>(labels, images);
    otsuKernel<<<BATCH, 256>>>();
    lossKernel<<<grid, 256>>>(preds, images);
    finalKernel<<<1, 32>>>(out);
}